// round 11
// baseline (speedup 1.0000x reference)
#include <cuda_runtime.h>
#include <cuda_bf16.h>
#include <cstdint>

// RepeatEncoder: LIF spiking neuron over T=32 repeated presentations of the
// same frame. Input [B=64, C=64, L=512] fp32 -> output [B, T=32, L, C] fp32.
//
// Per (b,l,c): x = in[b,c,l]; v=0; for t in 0..31:
//   v += (x - v)*0.5;  s = (v >= 1);  v = s ? 0 : v;  out[b,t,l,c] = s
//
// Wall time is pinned by the 256 MB/replay DRAM write drain (~5.9 TB/s);
// the ncu window already sits at the LTS byte cap. R10: Blackwell 256-bit
// streaming stores (st.global.cs.v8.f32, STG.E.256) halve store-instruction
// count -> smoother drain, lower LSU/issue pressure. Tile config = best
// measured (LT=32); each thread owns 8 consecutive channels so a warp emits
// 1 KB contiguous per store instruction. Coalesced smem input staging kept.

namespace {
constexpr int B  = 64;
constexpr int C  = 64;
constexpr int L  = 512;
constexpr int T  = 32;
constexpr int LT = 32;                 // l-tile per block
constexpr int THREADS = 256;           // = LT * (C/8)
constexpr int PITCH = LT + 1;          // smem pitch (33 floats)
}

__device__ __forceinline__ void stcs_v8(float* p,
    float a0, float a1, float a2, float a3,
    float a4, float a5, float a6, float a7) {
    asm volatile(
        "st.global.cs.v8.f32 [%0], {%1,%2,%3,%4,%5,%6,%7,%8};"
        :: "l"(p),
           "f"(a0), "f"(a1), "f"(a2), "f"(a3),
           "f"(a4), "f"(a5), "f"(a6), "f"(a7)
        : "memory");
}

__global__ void __launch_bounds__(THREADS)
lif_repeat_encoder_kernel(const float* __restrict__ in, float* __restrict__ out) {
    __shared__ float tile[C * PITCH];  // tile[c][ll], ~8.25 KB

    const int tid = threadIdx.x;
    const int bid = blockIdx.x;        // 0 .. B*(L/LT)-1 = 1023
    const int b   = bid >> 4;          // bid / (L/LT=16)
    const int l0  = (bid & 15) << 5;   // (bid % 16) * 32

    // ---- Coalesced load: input [B, C, L]; block needs [b, 0:64, l0:l0+32].
    // Each warp loads 32 consecutive floats (128B). 8 rows per thread.
    {
        const int ll = tid & 31;       // l within tile
        const int cr = tid >> 5;       // 0..7
        const float* src = in + ((size_t)b * C) * L + l0 + ll;
        #pragma unroll
        for (int i = 0; i < 8; ++i) {
            const int c = cr + i * 8;
            tile[c * PITCH + ll] = src[(size_t)c * L];
        }
    }
    __syncthreads();

    // ---- Compute + store: thread owns (ll, 8 consecutive channels).
    const int c8 = tid & 7;            // channel group 0..7
    const int ll = tid >> 3;           // l within tile 0..31
    const int c  = c8 * 8;
    const int l  = l0 + ll;

    float x0 = tile[(c + 0) * PITCH + ll];
    float x1 = tile[(c + 1) * PITCH + ll];
    float x2 = tile[(c + 2) * PITCH + ll];
    float x3 = tile[(c + 3) * PITCH + ll];
    float x4 = tile[(c + 4) * PITCH + ll];
    float x5 = tile[(c + 5) * PITCH + ll];
    float x6 = tile[(c + 6) * PITCH + ll];
    float x7 = tile[(c + 7) * PITCH + ll];

    float v0 = 0.f, v1 = 0.f, v2 = 0.f, v3 = 0.f;
    float v4 = 0.f, v5 = 0.f, v6 = 0.f, v7 = 0.f;

    // Output [B, T, L, C]: base at t=0, stride L*C floats per timestep.
    // Warp stores 1024B contiguous (8 lanes span one l-row of 64 channels).
    float* outp = out + ((size_t)b * T * L + l) * C + c;
    constexpr size_t strideT = (size_t)L * C;

    #pragma unroll
    for (int t = 0; t < T; ++t) {
        // v = v + (x - v)/tau, tau = 2 (mul by 0.5 is exact)
        v0 += (x0 - v0) * 0.5f;  v1 += (x1 - v1) * 0.5f;
        v2 += (x2 - v2) * 0.5f;  v3 += (x3 - v3) * 0.5f;
        v4 += (x4 - v4) * 0.5f;  v5 += (x5 - v5) * 0.5f;
        v6 += (x6 - v6) * 0.5f;  v7 += (x7 - v7) * 0.5f;

        const float s0 = (v0 >= 1.0f) ? 1.0f : 0.0f;
        const float s1 = (v1 >= 1.0f) ? 1.0f : 0.0f;
        const float s2 = (v2 >= 1.0f) ? 1.0f : 0.0f;
        const float s3 = (v3 >= 1.0f) ? 1.0f : 0.0f;
        const float s4 = (v4 >= 1.0f) ? 1.0f : 0.0f;
        const float s5 = (v5 >= 1.0f) ? 1.0f : 0.0f;
        const float s6 = (v6 >= 1.0f) ? 1.0f : 0.0f;
        const float s7 = (v7 >= 1.0f) ? 1.0f : 0.0f;

        v0 = (s0 != 0.0f) ? 0.0f : v0;  v1 = (s1 != 0.0f) ? 0.0f : v1;
        v2 = (s2 != 0.0f) ? 0.0f : v2;  v3 = (s3 != 0.0f) ? 0.0f : v3;
        v4 = (s4 != 0.0f) ? 0.0f : v4;  v5 = (s5 != 0.0f) ? 0.0f : v5;
        v6 = (s6 != 0.0f) ? 0.0f : v6;  v7 = (s7 != 0.0f) ? 0.0f : v7;

        // 256-bit streaming store (STG.E.256, evict-first).
        stcs_v8(outp + (size_t)t * strideT, s0, s1, s2, s3, s4, s5, s6, s7);
    }
}

extern "C" void kernel_launch(void* const* d_in, const int* in_sizes, int n_in,
                              void* d_out, int out_size) {
    (void)in_sizes; (void)n_in; (void)out_size;
    const float* in = (const float*)d_in[0];
    float* out = (float*)d_out;

    const int blocks = B * (L / LT);   // 1024
    lif_repeat_encoder_kernel<<<blocks, THREADS>>>(in, out);
}

// round 12
// speedup vs baseline: 1.0449x; 1.0449x over previous
#include <cuda_runtime.h>
#include <cuda_bf16.h>
#include <cstdint>

// RepeatEncoder: LIF spiking neuron over T=32 repeated presentations of the
// same frame. Input [B=64, C=64, L=512] fp32 -> output [B, T=32, L, C] fp32.
//
// Per (b,l,c): x = in[b,c,l]; v=0; for t in 0..31:
//   v += (x - v)*0.5;  s = (v >= 1);  v = s ? 0 : v;  out[b,t,l,c] = s
//
// Wall time pinned by the 256 MB/replay DRAM write drain (~6.2 TB/s).
// R11: exact best-known config (R8: LT=32, 512-thread CTAs, grid 1024,
// coalesced smem input staging, float4 stores) with ONE change: stores use
// st.global.wt (write-through) instead of .cs, pushing lines to DRAM eagerly
// so no dirty-L2 backlog remains at kernel end (targets the 2.8us wall-ncu
// flush gap). Warp stores cover 4 full 128B lines -> full-line writes.

namespace {
constexpr int B  = 64;
constexpr int C  = 64;
constexpr int L  = 512;
constexpr int T  = 32;
constexpr int LT = 32;                 // l-tile per block
constexpr int THREADS = 512;           // = LT * (C/4)
constexpr int PITCH = LT + 1;          // smem pitch (33 floats)
}

__device__ __forceinline__ void stg_wt_v4(float4* p, float4 v) {
    asm volatile(
        "st.global.wt.v4.f32 [%0], {%1,%2,%3,%4};"
        :: "l"(p), "f"(v.x), "f"(v.y), "f"(v.z), "f"(v.w)
        : "memory");
}

__global__ void __launch_bounds__(THREADS)
lif_repeat_encoder_kernel(const float* __restrict__ in, float* __restrict__ out) {
    __shared__ float tile[C * PITCH];  // tile[c][ll], pitch 33

    const int tid = threadIdx.x;
    const int bid = blockIdx.x;        // 0 .. B*(L/LT)-1 = 1023
    const int b   = bid >> 4;          // bid / (L/LT=16)
    const int l0  = (bid & 15) << 5;   // (bid % 16) * 32

    // ---- Coalesced load: input [B, C, L]; block needs [b, 0:64, l0:l0+32].
    // Each warp loads 32 consecutive floats (128B). 4 rows per thread.
    {
        const int ll = tid & 31;       // l within tile
        const int cr = tid >> 5;       // 0..15
        const float* src = in + ((size_t)b * C) * L + l0 + ll;
        #pragma unroll
        for (int i = 0; i < 4; ++i) {
            const int c = cr + i * 16;
            tile[c * PITCH + ll] = src[(size_t)c * L];
        }
    }
    __syncthreads();

    // ---- Compute + store: thread owns (ll, 4 consecutive channels).
    const int c4 = tid & 15;           // channel group 0..15
    const int ll = tid >> 4;           // l within tile 0..31
    const int c  = c4 * 4;
    const int l  = l0 + ll;

    const float x0 = tile[(c + 0) * PITCH + ll];
    const float x1 = tile[(c + 1) * PITCH + ll];
    const float x2 = tile[(c + 2) * PITCH + ll];
    const float x3 = tile[(c + 3) * PITCH + ll];

    float v0 = 0.f, v1 = 0.f, v2 = 0.f, v3 = 0.f;

    // Output [B, T, L, C]: base at t=0, stride L*C floats per timestep.
    // Warp stores 512B contiguous (4 full 128B lines) per timestep.
    float4* outp = reinterpret_cast<float4*>(
        out + ((size_t)b * T * L + l) * C + c);
    constexpr size_t strideT4 = (size_t)L * C / 4;

    #pragma unroll
    for (int t = 0; t < T; ++t) {
        // v = v + (x - v)/tau, tau = 2 (mul by 0.5 is exact)
        v0 += (x0 - v0) * 0.5f;
        v1 += (x1 - v1) * 0.5f;
        v2 += (x2 - v2) * 0.5f;
        v3 += (x3 - v3) * 0.5f;

        const float s0 = (v0 >= 1.0f) ? 1.0f : 0.0f;
        const float s1 = (v1 >= 1.0f) ? 1.0f : 0.0f;
        const float s2 = (v2 >= 1.0f) ? 1.0f : 0.0f;
        const float s3 = (v3 >= 1.0f) ? 1.0f : 0.0f;

        v0 = (s0 != 0.0f) ? 0.0f : v0;
        v1 = (s1 != 0.0f) ? 0.0f : v1;
        v2 = (s2 != 0.0f) ? 0.0f : v2;
        v3 = (s3 != 0.0f) ? 0.0f : v3;

        // Write-through store: eager DRAM drain, no dirty-L2 backlog.
        stg_wt_v4(outp + (size_t)t * strideT4, make_float4(s0, s1, s2, s3));
    }
}

extern "C" void kernel_launch(void* const* d_in, const int* in_sizes, int n_in,
                              void* d_out, int out_size) {
    (void)in_sizes; (void)n_in; (void)out_size;
    const float* in = (const float*)d_in[0];
    float* out = (float*)d_out;

    const int blocks = B * (L / LT);   // 1024
    lif_repeat_encoder_kernel<<<blocks, THREADS>>>(in, out);
}

// round 13
// speedup vs baseline: 1.0877x; 1.0409x over previous
#include <cuda_runtime.h>
#include <cuda_bf16.h>
#include <cstdint>

// RepeatEncoder: LIF spiking neuron over T=32 repeated presentations of the
// same frame. Input [B=64, C=64, L=512] fp32 -> output [B, T=32, L, C] fp32.
//
// Per (b,l,c): x = in[b,c,l]; v=0; for t in 0..31:
//   v += (x - v)*0.5;  s = (v >= 1);  v = s ? 0 : v;  out[b,t,l,c] = s
//
// CONVERGED CONFIG (best of R4-R11 sweep): wall time is pinned by the
// sustained DRAM write drain of the 256 MB output stream (~6.1 TB/s, the
// HBM3e write-mostly ceiling). Two different grids hit the same 43.5us
// wall; store-width (v8), write-through (.wt), and tile-size variations all
// measured neutral or worse. This is R6 exactly:
//  - coalesced smem-staged input (8 KB/CTA, 128B per-warp LDGs)
//  - perfectly coalesced float4 stores, 512B contiguous per warp
//  - st.global.cs (evict-first) so dirty L2 drains overlap graph replays
//  - LT=32 l-tile, 512-thread CTAs, grid 1024, 32 regs -> occ 4 CTAs/SM

namespace {
constexpr int B  = 64;
constexpr int C  = 64;
constexpr int L  = 512;
constexpr int T  = 32;
constexpr int LT = 32;                 // l-tile per block
constexpr int THREADS = 512;           // = LT * (C/4) compute units
constexpr int PITCH = LT + 1;          // smem pitch (33 floats) to limit conflicts
}

__global__ void __launch_bounds__(THREADS)
lif_repeat_encoder_kernel(const float* __restrict__ in, float* __restrict__ out) {
    __shared__ float tile[C * PITCH];  // tile[c][ll], pitch 33

    const int tid = threadIdx.x;
    const int bid = blockIdx.x;        // 0 .. B*(L/LT)-1 = 1023
    const int b   = bid >> 4;          // bid / (L/LT)
    const int l0  = (bid & 15) << 5;   // (bid % 16) * 32

    // ---- Coalesced load: input [B, C, L], this block needs [b, 0:64, l0:l0+32]
    // 4 iterations x 512 threads; each warp loads 32 consecutive floats (128B).
    {
        const int ll = tid & 31;       // l within tile
        const int cr = tid >> 5;       // 0..15
        const float* src = in + ((size_t)b * C) * L + l0 + ll;
        #pragma unroll
        for (int i = 0; i < 4; ++i) {
            const int c = cr + i * 16;
            tile[c * PITCH + ll] = src[(size_t)c * L];
        }
    }
    __syncthreads();

    // ---- Compute + store: thread owns (ll, c4) -> 4 consecutive channels
    const int c4 = tid & 15;           // channel group 0..15
    const int ll = tid >> 4;           // l within tile 0..31
    const int c  = c4 * 4;
    const int l  = l0 + ll;

    const float x0 = tile[(c + 0) * PITCH + ll];
    const float x1 = tile[(c + 1) * PITCH + ll];
    const float x2 = tile[(c + 2) * PITCH + ll];
    const float x3 = tile[(c + 3) * PITCH + ll];

    float v0 = 0.f, v1 = 0.f, v2 = 0.f, v3 = 0.f;

    // Output [B, T, L, C]: base at t=0, stride L*C floats per timestep.
    float4* outp = reinterpret_cast<float4*>(
        out + ((size_t)b * T * L + l) * C + c);
    constexpr size_t strideT4 = (size_t)L * C / 4;

    #pragma unroll
    for (int t = 0; t < T; ++t) {
        // v = v + (x - v)/tau, tau = 2 (mul by 0.5 is exact)
        v0 += (x0 - v0) * 0.5f;
        v1 += (x1 - v1) * 0.5f;
        v2 += (x2 - v2) * 0.5f;
        v3 += (x3 - v3) * 0.5f;

        const float s0 = (v0 >= 1.0f) ? 1.0f : 0.0f;
        const float s1 = (v1 >= 1.0f) ? 1.0f : 0.0f;
        const float s2 = (v2 >= 1.0f) ? 1.0f : 0.0f;
        const float s3 = (v3 >= 1.0f) ? 1.0f : 0.0f;

        v0 = (s0 != 0.0f) ? 0.0f : v0;
        v1 = (s1 != 0.0f) ? 0.0f : v1;
        v2 = (s2 != 0.0f) ? 0.0f : v2;
        v3 = (s3 != 0.0f) ? 0.0f : v3;

        // Streaming store: evict-first, this data is never re-read on-chip.
        __stcs(outp + (size_t)t * strideT4, make_float4(s0, s1, s2, s3));
    }
}

extern "C" void kernel_launch(void* const* d_in, const int* in_sizes, int n_in,
                              void* d_out, int out_size) {
    (void)in_sizes; (void)n_in; (void)out_size;
    const float* in = (const float*)d_in[0];
    float* out = (float*)d_out;

    const int blocks = B * (L / LT);   // 1024
    lif_repeat_encoder_kernel<<<blocks, THREADS>>>(in, out);
}

// round 14
// speedup vs baseline: 1.1030x; 1.0141x over previous
#include <cuda_runtime.h>
#include <cuda_bf16.h>
#include <cstdint>

// RepeatEncoder: LIF spiking neuron over T=32 repeated presentations of the
// same frame. Input [B=64, C=64, L=512] fp32 -> output [B, T=32, L, C] fp32.
//
// Per (b,l,c): x = in[b,c,l]; v=0; for t in 0..31:
//   v += (x - v)*0.5;  s = (v >= 1);  v = s ? 0 : v;  out[b,t,l,c] = s
//
// FINAL / CONVERGED (R4-R13 sweep): wall time is pinned by the sustained
// DRAM drain of the irreducible 256 MB fp32 output stream at ~6.1 TB/s
// (HBM3e write-mostly ceiling; LTS byte cap reached in-window). Falsified
// alternatives: coarser tiles (+6us, balance loss), 256-bit stores at lower
// occupancy (+4us), write-through (+2us, loses L2 write coalescing),
// default store policy (+2us, dirty-L2 backlog stalls graph replays).
// Winning ingredients:
//  - coalesced smem-staged input (8 KB/CTA, 128B per-warp LDGs)
//  - perfectly coalesced float4 stores, 512B contiguous per warp
//  - st.global.cs (evict-first) so dirty-L2 drain overlaps graph replays
//  - LT=32 l-tile, 512-thread CTAs, grid 1024, 32 regs -> 4 CTAs/SM
//  - exact arithmetic match to the JAX reference (rel_err == 0.0)

namespace {
constexpr int B  = 64;
constexpr int C  = 64;
constexpr int L  = 512;
constexpr int T  = 32;
constexpr int LT = 32;                 // l-tile per block
constexpr int THREADS = 512;           // = LT * (C/4) compute units
constexpr int PITCH = LT + 1;          // smem pitch (33 floats) to limit conflicts
}

__global__ void __launch_bounds__(THREADS)
lif_repeat_encoder_kernel(const float* __restrict__ in, float* __restrict__ out) {
    __shared__ float tile[C * PITCH];  // tile[c][ll], pitch 33

    const int tid = threadIdx.x;
    const int bid = blockIdx.x;        // 0 .. B*(L/LT)-1 = 1023
    const int b   = bid >> 4;          // bid / (L/LT)
    const int l0  = (bid & 15) << 5;   // (bid % 16) * 32

    // ---- Coalesced load: input [B, C, L], this block needs [b, 0:64, l0:l0+32]
    // 4 iterations x 512 threads; each warp loads 32 consecutive floats (128B).
    {
        const int ll = tid & 31;       // l within tile
        const int cr = tid >> 5;       // 0..15
        const float* src = in + ((size_t)b * C) * L + l0 + ll;
        #pragma unroll
        for (int i = 0; i < 4; ++i) {
            const int c = cr + i * 16;
            tile[c * PITCH + ll] = src[(size_t)c * L];
        }
    }
    __syncthreads();

    // ---- Compute + store: thread owns (ll, c4) -> 4 consecutive channels
    const int c4 = tid & 15;           // channel group 0..15
    const int ll = tid >> 4;           // l within tile 0..31
    const int c  = c4 * 4;
    const int l  = l0 + ll;

    const float x0 = tile[(c + 0) * PITCH + ll];
    const float x1 = tile[(c + 1) * PITCH + ll];
    const float x2 = tile[(c + 2) * PITCH + ll];
    const float x3 = tile[(c + 3) * PITCH + ll];

    float v0 = 0.f, v1 = 0.f, v2 = 0.f, v3 = 0.f;

    // Output [B, T, L, C]: base at t=0, stride L*C floats per timestep.
    float4* outp = reinterpret_cast<float4*>(
        out + ((size_t)b * T * L + l) * C + c);
    constexpr size_t strideT4 = (size_t)L * C / 4;

    #pragma unroll
    for (int t = 0; t < T; ++t) {
        // v = v + (x - v)/tau, tau = 2 (mul by 0.5 is exact)
        v0 += (x0 - v0) * 0.5f;
        v1 += (x1 - v1) * 0.5f;
        v2 += (x2 - v2) * 0.5f;
        v3 += (x3 - v3) * 0.5f;

        const float s0 = (v0 >= 1.0f) ? 1.0f : 0.0f;
        const float s1 = (v1 >= 1.0f) ? 1.0f : 0.0f;
        const float s2 = (v2 >= 1.0f) ? 1.0f : 0.0f;
        const float s3 = (v3 >= 1.0f) ? 1.0f : 0.0f;

        v0 = (s0 != 0.0f) ? 0.0f : v0;
        v1 = (s1 != 0.0f) ? 0.0f : v1;
        v2 = (s2 != 0.0f) ? 0.0f : v2;
        v3 = (s3 != 0.0f) ? 0.0f : v3;

        // Streaming store: evict-first, this data is never re-read on-chip.
        __stcs(outp + (size_t)t * strideT4, make_float4(s0, s1, s2, s3));
    }
}

extern "C" void kernel_launch(void* const* d_in, const int* in_sizes, int n_in,
                              void* d_out, int out_size) {
    (void)in_sizes; (void)n_in; (void)out_size;
    const float* in = (const float*)d_in[0];
    float* out = (float*)d_out;

    const int blocks = B * (L / LT);   // 1024
    lif_repeat_encoder_kernel<<<blocks, THREADS>>>(in, out);
}

// round 15
// speedup vs baseline: 1.1047x; 1.0015x over previous
#include <cuda_runtime.h>
#include <cuda_bf16.h>
#include <cstdint>

// RepeatEncoder: LIF spiking neuron over T=32 repeated presentations of the
// same frame. Input [B=64, C=64, L=512] fp32 -> output [B, T=32, L, C] fp32.
//
// Per (b,l,c): x = in[b,c,l]; v=0; for t in 0..31:
//   v += (x - v)*0.5;  s = (v >= 1);  v = s ? 0 : v;  out[b,t,l,c] = s
//
// Converged config (R6/R13): wall pinned by the sustained DRAM drain of the
// irreducible 256 MB output stream. R14 single change: all store addressing
// uses a single base pointer + constant immediate offsets (output < 4GB so
// offsets fit 32-bit), eliminating the per-store 64-bit IMAD chains that
// were consuming ~25% of the alu pipe / issue slots.
//  - coalesced smem-staged input (8 KB/CTA, 128B per-warp LDGs)
//  - perfectly coalesced float4 stores, 512B contiguous per warp
//  - st.global.cs (evict-first) so dirty-L2 drain overlaps graph replays
//  - LT=32 l-tile, 512-thread CTAs, grid 1024 -> 4 CTAs/SM, 2048 thr/SM

namespace {
constexpr int B  = 64;
constexpr int C  = 64;
constexpr int L  = 512;
constexpr int T  = 32;
constexpr int LT = 32;                 // l-tile per block
constexpr int THREADS = 512;           // = LT * (C/4) compute units
constexpr int PITCH = LT + 1;          // smem pitch (33 floats)
}

__global__ void __launch_bounds__(THREADS)
lif_repeat_encoder_kernel(const float* __restrict__ in, float* __restrict__ out) {
    __shared__ float tile[C * PITCH];  // tile[c][ll], pitch 33

    const int tid = threadIdx.x;
    const int bid = blockIdx.x;        // 0 .. 1023
    const int b   = bid >> 4;          // bid / (L/LT)
    const int l0  = (bid & 15) << 5;   // (bid % 16) * 32

    // ---- Coalesced load: input [B, C, L]; block needs [b, 0:64, l0:l0+32].
    // Each warp loads 32 consecutive floats (128B). 4 rows per thread.
    {
        const int ll = tid & 31;       // l within tile
        const int cr = tid >> 5;       // 0..15
        const float* src = in + ((size_t)b * C) * L + l0 + ll;
        #pragma unroll
        for (int i = 0; i < 4; ++i) {
            const int c = cr + i * 16;
            tile[c * PITCH + ll] = src[(size_t)c * L];
        }
    }
    __syncthreads();

    // ---- Compute + store: thread owns (ll, c4) -> 4 consecutive channels.
    const int c4 = tid & 15;           // channel group 0..15
    const int ll = tid >> 4;           // l within tile 0..31
    const int c  = c4 * 4;
    const int l  = l0 + ll;

    const float x0 = tile[(c + 0) * PITCH + ll];
    const float x1 = tile[(c + 1) * PITCH + ll];
    const float x2 = tile[(c + 2) * PITCH + ll];
    const float x3 = tile[(c + 3) * PITCH + ll];

    float v0 = 0.f, v1 = 0.f, v2 = 0.f, v3 = 0.f;

    // Output [B, T, L, C]: single base pointer; every store addressed as
    // [base + compile-time-constant offset] (offsets < 2^28 bytes).
    // 32-bit offset math: base index fits u32 (max < 64M elements).
    const unsigned base_f = ((unsigned)b * T * L + (unsigned)l) * C + (unsigned)c;
    char* const outb = reinterpret_cast<char*>(out) + (size_t)base_f * 4u;
    constexpr unsigned strideT_bytes = (unsigned)L * C * 4u;  // 131072

    #pragma unroll
    for (int t = 0; t < T; ++t) {
        // v = v + (x - v)/tau, tau = 2 (mul by 0.5 is exact)
        v0 += (x0 - v0) * 0.5f;
        v1 += (x1 - v1) * 0.5f;
        v2 += (x2 - v2) * 0.5f;
        v3 += (x3 - v3) * 0.5f;

        const float s0 = (v0 >= 1.0f) ? 1.0f : 0.0f;
        const float s1 = (v1 >= 1.0f) ? 1.0f : 0.0f;
        const float s2 = (v2 >= 1.0f) ? 1.0f : 0.0f;
        const float s3 = (v3 >= 1.0f) ? 1.0f : 0.0f;

        v0 = (s0 != 0.0f) ? 0.0f : v0;
        v1 = (s1 != 0.0f) ? 0.0f : v1;
        v2 = (s2 != 0.0f) ? 0.0f : v2;
        v3 = (s3 != 0.0f) ? 0.0f : v3;

        // Streaming store, evict-first; address = base + constant offset so
        // ptxas folds the offset into the STG immediate (no per-store IMAD).
        float4* dst = reinterpret_cast<float4*>(outb + (unsigned)t * strideT_bytes);
        __stcs(dst, make_float4(s0, s1, s2, s3));
    }
}

extern "C" void kernel_launch(void* const* d_in, const int* in_sizes, int n_in,
                              void* d_out, int out_size) {
    (void)in_sizes; (void)n_in; (void)out_size;
    const float* in = (const float*)d_in[0];
    float* out = (float*)d_out;

    const int blocks = B * (L / LT);   // 1024
    lif_repeat_encoder_kernel<<<blocks, THREADS>>>(in, out);
}